// round 9
// baseline (speedup 1.0000x reference)
#include <cuda_runtime.h>
#include <cuda_fp16.h>
#include <math.h>
#include <stdint.h>

// Problem constants
constexpr int B_ = 4, S_ = 4096, D_ = 64;
constexpr int MT = 64;            // q rows per tile (one phase)
constexpr int NT = 128;           // keys per k-tile
constexpr float QSCALE = 0.18033688011112042f;  // 0.125 * log2(e), folded into Q

// ---- global scratch (allocation-free rule) ----
__device__ __align__(16) __half g_Qh[B_*S_*D_];
__device__ __align__(16) __half g_Kh[B_*S_*D_];
__device__ __align__(16) __half g_Vh[B_*S_*D_];
__device__ __align__(16) float g_padneg[B_*S_];   // 0.0 (keep) or -inf (masked)
__device__ float g_part[256][D_];                 // V_p column sums per proj block

// ---- f32x2 helpers (proj kernel) ----
using u64_t = unsigned long long;
__device__ __forceinline__ u64_t fma2(u64_t a, u64_t b, u64_t c) {
    u64_t d; asm("fma.rn.f32x2 %0, %1, %2, %3;" : "=l"(d) : "l"(a), "l"(b), "l"(c)); return d;
}
__device__ __forceinline__ float2 unpack2(u64_t v) {
    float2 r; asm("mov.b64 {%0, %1}, %2;" : "=f"(r.x), "=f"(r.y) : "l"(v)); return r;
}

__device__ __forceinline__ uint32_t smem_u32(const void* p) {
    uint32_t a;
    asm("{ .reg .u64 t; cvta.to.shared.u64 t, %1; cvt.u32.u64 %0, t; }" : "=r"(a) : "l"(p));
    return a;
}

// ---- mma.sync / ldmatrix / misc PTX ----
__device__ __forceinline__ void ldm_x4(uint32_t* r, uint32_t a) {
    asm volatile("ldmatrix.sync.aligned.m8n8.x4.shared.b16 {%0,%1,%2,%3}, [%4];"
                 : "=r"(r[0]), "=r"(r[1]), "=r"(r[2]), "=r"(r[3]) : "r"(a));
}
__device__ __forceinline__ void ldm_x4_t(uint32_t* r, uint32_t a) {
    asm volatile("ldmatrix.sync.aligned.m8n8.x4.trans.shared.b16 {%0,%1,%2,%3}, [%4];"
                 : "=r"(r[0]), "=r"(r[1]), "=r"(r[2]), "=r"(r[3]) : "r"(a));
}
__device__ __forceinline__ void mma_f16(float* c, const uint32_t* a, const uint32_t* b) {
    asm volatile("mma.sync.aligned.m16n8k16.row.col.f32.f16.f16.f32 "
                 "{%0,%1,%2,%3}, {%4,%5,%6,%7}, {%8,%9}, {%0,%1,%2,%3};"
                 : "+f"(c[0]), "+f"(c[1]), "+f"(c[2]), "+f"(c[3])
                 : "r"(a[0]), "r"(a[1]), "r"(a[2]), "r"(a[3]), "r"(b[0]), "r"(b[1]));
}
__device__ __forceinline__ float ex2(float x) {
    float y; asm("ex2.approx.f32 %0, %1;" : "=f"(y) : "f"(x)); return y;
}
// pack two fp32 -> fp16x2; second arg lands in the LOW half
__device__ __forceinline__ uint32_t cvt_f16x2(float hi, float lo) {
    uint32_t r; asm("cvt.rn.f16x2.f32 %0, %1, %2;" : "=r"(r) : "f"(hi), "f"(lo)); return r;
}
__device__ __forceinline__ void cpa16(uint32_t dst, const void* src) {
    asm volatile("cp.async.cg.shared.global [%0], [%1], 16;" :: "r"(dst), "l"(src));
}
#define CP_COMMIT() asm volatile("cp.async.commit_group;" ::: "memory")
#define CP_WAIT0()  asm volatile("cp.async.wait_group 0;" ::: "memory")

// ---------------------------------------------------------------------------
// Kernel 0: detect pad_mask dtype (every block scans the first 16384 bytes =
// min buffer size), then each block converts its 256-element slice to the
// canonical float mask: 0.0 = keep, -inf = masked. 64 blocks, no cross-block dep.
// ---------------------------------------------------------------------------
__global__ __launch_bounds__(256) void detect_pad_kernel(const void* __restrict__ pv)
{
    __shared__ int f[2];
    const int t = threadIdx.x;
    if (t < 2) f[t] = 0;
    __syncthreads();
    const uint4* p4 = reinterpret_cast<const uint4*>(pv);   // 1024 x 16B
    uint32_t ge2 = 0, odd = 0;
    #pragma unroll
    for (int i = t; i < 1024; i += 256) {
        uint4 v = p4[i];
        uint32_t o = v.x | v.y | v.z | v.w;
        ge2 |= o & 0xFEFEFEFEu;     // any byte >= 2 anywhere
        odd |= o & 0xFFFFFF00u;     // any nonzero byte at idx%4 != 0
    }
    if (ge2) atomicOr(&f[0], 1);
    if (odd) atomicOr(&f[1], 1);
    __syncthreads();
    const int kind = f[0] ? 2 : (f[1] ? 0 : 1);   // 0=u8, 1=i32, 2=f32
    const float NEGINF = __int_as_float(0xff800000);
    const int i = blockIdx.x * 256 + t;
    bool m;
    if (kind == 0)      m = ((const unsigned char*)pv)[i] != 0;
    else if (kind == 1) m = ((const int*)pv)[i] != 0;
    else                m = ((const float*)pv)[i] != 0.f;
    g_padneg[i] = m ? NEGINF : 0.f;
}

// ---------------------------------------------------------------------------
// Kernel 1: fused QKV projection + popularity modulation -> single fp16,
// plus per-block V_p column sums. 256 blocks x 128 threads; 2 threads per row
// (each owns 32 of the 64 output features).
// ---------------------------------------------------------------------------
__global__ __launch_bounds__(128) void proj_kernel(
    const float* __restrict__ E,  const float* __restrict__ PK, const float* __restrict__ PV,
    const float* __restrict__ Wq, const float* __restrict__ bq,
    const float* __restrict__ Wk, const float* __restrict__ bk,
    const float* __restrict__ Wv, const float* __restrict__ bv)
{
    __shared__ float Wsm[3][D_ * D_];     // 48 KB; Wsm[0] reused as reduction scratch
    const int t = threadIdx.x;
    const int rloc = t & 63, chalf = t >> 6;
    const int cbase = chalf * 32;
    const size_t g = (size_t)blockIdx.x * 64 + rloc;

    {
        const float* Ws[3] = {Wq, Wk, Wv};
        #pragma unroll
        for (int m = 0; m < 3; m++) {
            float4* dst = reinterpret_cast<float4*>(Wsm[m]);
            const float4* src = reinterpret_cast<const float4*>(Ws[m]);
            #pragma unroll
            for (int i = 0; i < 8; i++) dst[t + i * 128] = src[t + i * 128];
        }
    }
    __syncthreads();

    u64_t e2[32];
    {
        const ulonglong2* er = reinterpret_cast<const ulonglong2*>(E + g * D_);
        #pragma unroll
        for (int i = 0; i < 16; i++) { ulonglong2 v = er[i]; e2[2*i] = v.x; e2[2*i+1] = v.y; }
    }

    const float* bsx[3] = {bq, bk, bv};
    __half* oh3[3] = {g_Qh, g_Kh, g_Vh};
    float outv[32];

    #pragma unroll
    for (int m = 0; m < 3; m++) {
        for (int c = 0; c < 32; c++) {
            const ulonglong2* wr = reinterpret_cast<const ulonglong2*>(Wsm[m] + (cbase + c) * D_);
            u64_t a0 = 0ull, a1 = 0ull;
            #pragma unroll
            for (int d8 = 0; d8 < 16; d8++) {
                ulonglong2 w = wr[d8];
                a0 = fma2(e2[2*d8],   w.x, a0);
                a1 = fma2(e2[2*d8+1], w.y, a1);
            }
            float2 p0 = unpack2(a0), p1 = unpack2(a1);
            outv[c] = bsx[m][cbase + c] + ((p0.x + p0.y) + (p1.x + p1.y));
        }
        if (m == 0) {
            #pragma unroll
            for (int c = 0; c < 32; c++) outv[c] *= QSCALE;
        } else {
            const float* mod = (m == 1 ? PK : PV) + g * D_ + cbase;
            #pragma unroll
            for (int c = 0; c < 32; c++) outv[c] *= mod[c];
        }
        unsigned short hb[32];
        #pragma unroll
        for (int c = 0; c < 32; c++)
            hb[c] = __half_as_ushort(__float2half_rn(outv[c]));
        uint4* oh = reinterpret_cast<uint4*>(oh3[m] + g * D_ + cbase);
        const uint4* sh = reinterpret_cast<const uint4*>(hb);
        #pragma unroll
        for (int i = 0; i < 4; i++) oh[i] = sh[i];
    }

    // ---- meanV partial: outv holds this thread's half-row of fp32 V_p ----
    __syncthreads();                       // everyone done reading Wsm
    float* red = Wsm[0];                   // 64 x 64 f32 = 16 KB
    #pragma unroll
    for (int i = 0; i < 8; i++)
        reinterpret_cast<float4*>(red + rloc * 64 + cbase)[i] =
            make_float4(outv[4*i], outv[4*i+1], outv[4*i+2], outv[4*i+3]);
    __syncthreads();
    if (t < 64) {
        float a = 0.f;
        #pragma unroll 8
        for (int r = 0; r < 64; r++) a += red[r * 64 + t];
        g_part[blockIdx.x][t] = a;
    }
}

// ---------------------------------------------------------------------------
// Kernel 2: single-fp16 mma.sync flash attention, cp.async double-buffered.
// CTA = 512 threads = 4 row-warps x 4 key-quarters over a 64-row q-tile
// (16 warps/SM = 4/SMSP for latency hiding; <=128 regs/thread).
// Pair scheduling (qt, 63-qt): exactly 33 k-tiles per CTA.
// meanV (fallback for fully-masked rows) computed in the prologue from g_part.
// ---------------------------------------------------------------------------
constexpr int SM_QH   = 0;                      // 64 x 128B
constexpr int SM_KV   = 8192;                   // 2 stages x (K 16KB + V 16KB)
constexpr int STG_SZ  = 32768;
constexpr int OFF_K   = 0, OFF_V = 16384;
constexpr int SM_PADB = SM_KV + 2 * STG_SZ;     // 73728, 2 x 512B
constexpr int SM_LSM  = SM_PADB + 1024;         // 74752, 4 x 64 f32
constexpr int SM_MNV  = SM_LSM + 1024;          // 75776, 64 f32
constexpr int SM_MRG  = SM_KV;                  // merge overlays stages (drained)
constexpr int SM_TOTAL = SM_MNV + 256;          // 76032

__global__ __launch_bounds__(512, 1) void attn_mma_kernel(float* __restrict__ out)
{
    extern __shared__ char sm[];
    const uint32_t smb = smem_u32(sm);
    const int tid = threadIdx.x, wid = tid >> 5, lane = tid & 31;
    const int wr = wid & 3, wc = wid >> 2;        // row-warp, key-quarter (0..3)
    const int b = blockIdx.y;
    const int g8 = lane >> 3, l8 = lane & 7, l4 = lane >> 2, lq = lane & 3;
    float* lsm  = reinterpret_cast<float*>(sm + SM_LSM);
    float* mnv  = reinterpret_cast<float*>(sm + SM_MNV);
    float* mrg  = reinterpret_cast<float*>(sm + SM_MRG);

    // ---- meanV for this batch (sum of 64 proj-block partials) ----
    if (tid < 64) {
        float a = 0.f;
        #pragma unroll 8
        for (int i = 0; i < 64; i++) a += g_part[b * 64 + i][tid];
        mnv[tid] = a * (1.0f / (float)S_);
    }

    #pragma unroll 1
    for (int phase = 0; phase < 2; phase++) {
        const int qt = phase ? (63 - blockIdx.x) : blockIdx.x;
        const int qbase = qt * MT;
        const int nkt = (qt >> 1) + 1;

        __syncthreads();   // prev phase merge reads done (and mnv visible); smem reusable

        // ---- prologue: async-copy Q + k-tile 0 into stage 0 ----
        {
            const uint4* qh4 = reinterpret_cast<const uint4*>(g_Qh + ((size_t)b * S_ + qbase) * D_);
            {
                int i = tid;                       // 512 chunks
                int row = i >> 3, c = i & 7;
                uint32_t sw = row * 128 + (((uint32_t)(c ^ (row & 7))) << 4);
                cpa16(smb + SM_QH + sw, qh4 + i);
            }
            const __half* srcs[2] = {g_Kh + (size_t)b * S_ * D_, g_Vh + (size_t)b * S_ * D_};
            #pragma unroll
            for (int t2 = 0; t2 < 2; t2++) {
                #pragma unroll
                for (int it = 0; it < 2; it++) {
                    int i = tid + it * 512;        // 1024 chunks per tile
                    int row = i >> 3, c = i & 7;
                    uint32_t dst = smb + SM_KV + t2 * 16384 + row * 128 + (((uint32_t)(c ^ (row & 7))) << 4);
                    cpa16(dst, reinterpret_cast<const uint4*>(srcs[t2]) + i);
                }
            }
            if (tid < 32)
                cpa16(smb + SM_PADB + tid * 16, (const char*)(g_padneg + b * S_) + tid * 16);
            CP_COMMIT();
        }
        CP_WAIT0();
        __syncthreads();

        // ---- Q A-fragments, 4 d-chunks of 16 ----
        uint32_t qh[4][4];
        {
            const int row = wr * 16 + (g8 & 1) * 8 + l8;
            #pragma unroll
            for (int dc = 0; dc < 4; dc++) {
                const int c = 2 * dc + (g8 >> 1);
                ldm_x4(qh[dc], smb + SM_QH + row * 128 + (((uint32_t)(c ^ (row & 7))) << 4));
            }
        }

        float OC[8][4];
        #pragma unroll
        for (int i = 0; i < 8; i++)
            { OC[i][0] = 0.f; OC[i][1] = 0.f; OC[i][2] = 0.f; OC[i][3] = 0.f; }
        float rs0 = 0.f, rs1 = 0.f;
        const int q0 = qbase + wr * 16 + l4, q1 = q0 + 8;
        const int kb0 = wc * 32;

        #pragma unroll 1
        for (int j = 0; j < nkt; j++) {
            const int st = j & 1;
            const uint32_t stb = smb + SM_KV + st * STG_SZ;
            const float* padsm = reinterpret_cast<const float*>(sm + SM_PADB + st * 512);
            const int kt = j * NT;

            // issue copy for tile j+1 into the other stage (overlaps compute)
            if (j + 1 < nkt) {
                const int ktn = (j + 1) * NT;
                const uint32_t nstb = smb + SM_KV + ((j + 1) & 1) * STG_SZ;
                const __half* srcs[2] = {g_Kh + ((size_t)b * S_ + ktn) * D_,
                                         g_Vh + ((size_t)b * S_ + ktn) * D_};
                #pragma unroll
                for (int t2 = 0; t2 < 2; t2++) {
                    #pragma unroll
                    for (int it = 0; it < 2; it++) {
                        int i = tid + it * 512;
                        int row = i >> 3, c = i & 7;
                        uint32_t dst = nstb + t2 * 16384 + row * 128 + (((uint32_t)(c ^ (row & 7))) << 4);
                        cpa16(dst, reinterpret_cast<const uint4*>(srcs[t2]) + i);
                    }
                }
                if (tid < 32)
                    cpa16(smb + SM_PADB + ((j + 1) & 1) * 512 + tid * 16,
                          (const char*)(g_padneg + b * S_ + ktn) + tid * 16);
                CP_COMMIT();
            }

            // ---- S = Q K^T (single fp16), this warp's 32-key quarter ----
            float SC[4][4];
            #pragma unroll
            for (int i = 0; i < 4; i++)
                { SC[i][0] = 0.f; SC[i][1] = 0.f; SC[i][2] = 0.f; SC[i][3] = 0.f; }
            {
                const int krow0 = kb0 + (g8 >> 1) * 8 + l8;
                #pragma unroll
                for (int dc = 0; dc < 4; dc++) {
                    #pragma unroll
                    for (int kp = 0; kp < 2; kp++) {
                        const int row = krow0 + kp * 16;
                        const int c = 2 * dc + (g8 & 1);
                        uint32_t bh[4];
                        ldm_x4(bh, stb + OFF_K + row * 128 + (((uint32_t)(c ^ (row & 7))) << 4));
                        mma_f16(SC[2*kp],   qh[dc], bh);
                        mma_f16(SC[2*kp+1], qh[dc], bh + 2);
                    }
                }
            }

            // ---- mask + ex2 + C->A fragment conversion ----
            uint32_t Ph[2][4];
            if (j < nkt - 1) {
                #pragma unroll
                for (int n = 0; n < 4; n++) {
                    const int colb = kb0 + n * 8 + 2 * lq;
                    const float m0 = padsm[colb], m1 = padsm[colb + 1];
                    const float p00 = ex2(SC[n][0] + m0);
                    const float p01 = ex2(SC[n][1] + m1);
                    const float p10 = ex2(SC[n][2] + m0);
                    const float p11 = ex2(SC[n][3] + m1);
                    const uint32_t hA = cvt_f16x2(p01, p00);
                    const uint32_t hB = cvt_f16x2(p11, p10);
                    const float2 fA = __half22float2(*reinterpret_cast<const half2*>(&hA));
                    const float2 fB = __half22float2(*reinterpret_cast<const half2*>(&hB));
                    rs0 += fA.x + fA.y;
                    rs1 += fB.x + fB.y;
                    const int kc = n >> 1, sub = (n & 1) * 2;
                    Ph[kc][sub] = hA; Ph[kc][sub + 1] = hB;
                }
            } else {
                #pragma unroll
                for (int n = 0; n < 4; n++) {
                    const int colb = kb0 + n * 8 + 2 * lq;
                    const int key = kt + colb;
                    const float m0 = padsm[colb], m1 = padsm[colb + 1];
                    const float p00 = (key     <= q0) ? ex2(SC[n][0] + m0) : 0.f;
                    const float p01 = (key + 1 <= q0) ? ex2(SC[n][1] + m1) : 0.f;
                    const float p10 = (key     <= q1) ? ex2(SC[n][2] + m0) : 0.f;
                    const float p11 = (key + 1 <= q1) ? ex2(SC[n][3] + m1) : 0.f;
                    const uint32_t hA = cvt_f16x2(p01, p00);
                    const uint32_t hB = cvt_f16x2(p11, p10);
                    const float2 fA = __half22float2(*reinterpret_cast<const half2*>(&hA));
                    const float2 fB = __half22float2(*reinterpret_cast<const half2*>(&hB));
                    rs0 += fA.x + fA.y;
                    rs1 += fB.x + fB.y;
                    const int kc = n >> 1, sub = (n & 1) * 2;
                    Ph[kc][sub] = hA; Ph[kc][sub + 1] = hB;
                }
            }

            // ---- O += P V (V via ldmatrix.trans) ----
            {
                const int vrow0 = kb0 + (g8 & 1) * 8 + l8;
                #pragma unroll
                for (int kc = 0; kc < 2; kc++) {
                    #pragma unroll
                    for (int ndp = 0; ndp < 4; ndp++) {
                        const int row = vrow0 + kc * 16;
                        const int c = 2 * ndp + (g8 >> 1);
                        uint32_t bh[4];
                        ldm_x4_t(bh, stb + OFF_V + row * 128 + (((uint32_t)(c ^ (row & 7))) << 4));
                        mma_f16(OC[2*ndp],   Ph[kc], bh);
                        mma_f16(OC[2*ndp+1], Ph[kc], bh + 2);
                    }
                }
            }

            if (j + 1 < nkt) CP_WAIT0();
            __syncthreads();
        }

        // ---- merge the four key-quarters (ADD; no rescaling needed) ----
        rs0 += __shfl_xor_sync(0xFFFFFFFFu, rs0, 1);
        rs0 += __shfl_xor_sync(0xFFFFFFFFu, rs0, 2);
        rs1 += __shfl_xor_sync(0xFFFFFFFFu, rs1, 1);
        rs1 += __shfl_xor_sync(0xFFFFFFFFu, rs1, 2);
        if (lq == 0) {
            lsm[wc * 64 + wr * 16 + l4]     = rs0;
            lsm[wc * 64 + wr * 16 + 8 + l4] = rs1;
        }
        if (wc != 0) {
            float* mq = mrg + (wc - 1) * 4096;
            const int r0 = wr * 16 + l4;
            #pragma unroll
            for (int nd = 0; nd < 8; nd++) {
                const int d0 = nd * 8 + 2 * lq;
                *reinterpret_cast<float2*>(&mq[r0 * 64 + d0])       = make_float2(OC[nd][0], OC[nd][1]);
                *reinterpret_cast<float2*>(&mq[(r0 + 8) * 64 + d0]) = make_float2(OC[nd][2], OC[nd][3]);
            }
        }
        __syncthreads();
        if (wc == 0) {
            const int r0 = wr * 16 + l4;
            const float lt0 = lsm[r0] + lsm[64 + r0] + lsm[128 + r0] + lsm[192 + r0];
            const float lt1 = lsm[r0 + 8] + lsm[64 + r0 + 8] + lsm[128 + r0 + 8] + lsm[192 + r0 + 8];
            const bool am0 = (lt0 == 0.f), am1 = (lt1 == 0.f);
            const float inv0 = am0 ? 0.f : 1.f / lt0;
            const float inv1 = am1 ? 0.f : 1.f / lt1;
            const int qr0 = qbase + r0, qr1 = qr0 + 8;
            #pragma unroll
            for (int nd = 0; nd < 8; nd++) {
                const int d0 = nd * 8 + 2 * lq;
                float a0 = OC[nd][0], a1 = OC[nd][1], a2 = OC[nd][2], a3 = OC[nd][3];
                #pragma unroll
                for (int qq = 0; qq < 3; qq++) {
                    const float* mq = mrg + qq * 4096;
                    const float2 m0v = *reinterpret_cast<const float2*>(&mq[r0 * 64 + d0]);
                    const float2 m1v = *reinterpret_cast<const float2*>(&mq[(r0 + 8) * 64 + d0]);
                    a0 += m0v.x; a1 += m0v.y; a2 += m1v.x; a3 += m1v.y;
                }
                float2 o0, o1;
                if (am0) o0 = make_float2(mnv[d0], mnv[d0 + 1]);
                else     o0 = make_float2(a0 * inv0, a1 * inv0);
                if (am1) o1 = make_float2(mnv[d0], mnv[d0 + 1]);
                else     o1 = make_float2(a2 * inv1, a3 * inv1);
                *reinterpret_cast<float2*>(&out[((size_t)b * S_ + qr0) * D_ + d0]) = o0;
                *reinterpret_cast<float2*>(&out[((size_t)b * S_ + qr1) * D_ + d0]) = o1;
            }
        }
    }
}

// ---------------------------------------------------------------------------
extern "C" void kernel_launch(void* const* d_in, const int* in_sizes, int n_in,
                              void* d_out, int out_size)
{
    const float* E  = (const float*)d_in[0];
    const float* PK = (const float*)d_in[1];
    const float* PV = (const float*)d_in[2];
    const float* Wq = (const float*)d_in[3];
    const float* bq = (const float*)d_in[4];
    const float* Wk = (const float*)d_in[5];
    const float* bk = (const float*)d_in[6];
    const float* Wv = (const float*)d_in[7];
    const float* bv = (const float*)d_in[8];
    const void*  pad = d_in[9];
    float* out = (float*)d_out;

    cudaFuncSetAttribute(attn_mma_kernel, cudaFuncAttributeMaxDynamicSharedMemorySize, SM_TOTAL);

    detect_pad_kernel<<<64, 256>>>(pad);
    proj_kernel<<<256, 128>>>(E, PK, PV, Wq, bq, Wk, bk, Wv, bv);
    attn_mma_kernel<<<dim3(32, B_), 512, SM_TOTAL>>>(out);
}

// round 10
// speedup vs baseline: 1.0649x; 1.0649x over previous
#include <cuda_runtime.h>
#include <cuda_fp16.h>
#include <math.h>
#include <stdint.h>

// Problem constants
constexpr int B_ = 4, S_ = 4096, D_ = 64;
constexpr int MT = 64;            // q rows per tile (one phase)
constexpr int NT = 128;           // keys per k-tile
constexpr float QSCALE = 0.18033688011112042f;  // 0.125 * log2(e), folded into Q

// ---- global scratch (allocation-free rule) ----
__device__ __align__(16) __half g_Qh[B_*S_*D_];
__device__ __align__(16) __half g_Kh[B_*S_*D_];
__device__ __align__(16) __half g_Vh[B_*S_*D_];
__device__ __align__(16) float g_padneg[B_*S_];   // 0.0 (keep) or -inf (masked)
__device__ float g_part[256][D_];                 // V_p column sums per proj block

// ---- f32x2 helpers (proj kernel) ----
using u64_t = unsigned long long;
__device__ __forceinline__ u64_t fma2(u64_t a, u64_t b, u64_t c) {
    u64_t d; asm("fma.rn.f32x2 %0, %1, %2, %3;" : "=l"(d) : "l"(a), "l"(b), "l"(c)); return d;
}
__device__ __forceinline__ float2 unpack2(u64_t v) {
    float2 r; asm("mov.b64 {%0, %1}, %2;" : "=f"(r.x), "=f"(r.y) : "l"(v)); return r;
}

__device__ __forceinline__ uint32_t smem_u32(const void* p) {
    uint32_t a;
    asm("{ .reg .u64 t; cvta.to.shared.u64 t, %1; cvt.u32.u64 %0, t; }" : "=r"(a) : "l"(p));
    return a;
}

// ---- mma.sync / ldmatrix / misc PTX ----
__device__ __forceinline__ void ldm_x4(uint32_t* r, uint32_t a) {
    asm volatile("ldmatrix.sync.aligned.m8n8.x4.shared.b16 {%0,%1,%2,%3}, [%4];"
                 : "=r"(r[0]), "=r"(r[1]), "=r"(r[2]), "=r"(r[3]) : "r"(a));
}
__device__ __forceinline__ void ldm_x4_t(uint32_t* r, uint32_t a) {
    asm volatile("ldmatrix.sync.aligned.m8n8.x4.trans.shared.b16 {%0,%1,%2,%3}, [%4];"
                 : "=r"(r[0]), "=r"(r[1]), "=r"(r[2]), "=r"(r[3]) : "r"(a));
}
__device__ __forceinline__ void mma_f16(float* c, const uint32_t* a, const uint32_t* b) {
    asm volatile("mma.sync.aligned.m16n8k16.row.col.f32.f16.f16.f32 "
                 "{%0,%1,%2,%3}, {%4,%5,%6,%7}, {%8,%9}, {%0,%1,%2,%3};"
                 : "+f"(c[0]), "+f"(c[1]), "+f"(c[2]), "+f"(c[3])
                 : "r"(a[0]), "r"(a[1]), "r"(a[2]), "r"(a[3]), "r"(b[0]), "r"(b[1]));
}
__device__ __forceinline__ float ex2(float x) {
    float y; asm("ex2.approx.f32 %0, %1;" : "=f"(y) : "f"(x)); return y;
}
// pack two fp32 -> fp16x2; second arg lands in the LOW half
__device__ __forceinline__ uint32_t cvt_f16x2(float hi, float lo) {
    uint32_t r; asm("cvt.rn.f16x2.f32 %0, %1, %2;" : "=r"(r) : "f"(hi), "f"(lo)); return r;
}
__device__ __forceinline__ void cpa16(uint32_t dst, const void* src) {
    asm volatile("cp.async.cg.shared.global [%0], [%1], 16;" :: "r"(dst), "l"(src));
}
#define CP_COMMIT() asm volatile("cp.async.commit_group;" ::: "memory")
#define CP_WAIT0()  asm volatile("cp.async.wait_group 0;" ::: "memory")

// ---------------------------------------------------------------------------
// Kernel 1: fused pad-mask canonicalization + QKV projection + popularity
// modulation -> single fp16, plus per-block V_p column sums.
// 256 blocks x 128 threads; 2 threads per row (each owns 32 output features).
// Each block independently detects the pad dtype by scanning the first
// 16384 bytes (minimum possible buffer size; hot in L2), then converts its
// own 64 mask entries to the canonical additive 0/-inf float form.
// ---------------------------------------------------------------------------
__global__ __launch_bounds__(128) void proj_kernel(
    const float* __restrict__ E,  const float* __restrict__ PK, const float* __restrict__ PV,
    const float* __restrict__ Wq, const float* __restrict__ bq,
    const float* __restrict__ Wk, const float* __restrict__ bk,
    const float* __restrict__ Wv, const float* __restrict__ bv,
    const void* __restrict__ pad)
{
    __shared__ float Wsm[3][D_ * D_];     // 48 KB; Wsm[0] reused as reduction scratch
    __shared__ int f[2];
    const int t = threadIdx.x;
    const int rloc = t & 63, chalf = t >> 6;
    const int cbase = chalf * 32;
    const size_t g = (size_t)blockIdx.x * 64 + rloc;

    if (t < 2) f[t] = 0;

    // ---- stage W matrices ----
    {
        const float* Ws[3] = {Wq, Wk, Wv};
        #pragma unroll
        for (int m = 0; m < 3; m++) {
            float4* dst = reinterpret_cast<float4*>(Wsm[m]);
            const float4* src = reinterpret_cast<const float4*>(Ws[m]);
            #pragma unroll
            for (int i = 0; i < 8; i++) dst[t + i * 128] = src[t + i * 128];
        }
    }

    // ---- pad dtype detection (independent per block; 16KB scan) ----
    {
        const uint4* p4 = reinterpret_cast<const uint4*>(pad);   // 1024 x 16B
        uint32_t ge2 = 0, odd = 0;
        #pragma unroll
        for (int i = t; i < 1024; i += 128) {
            uint4 v = p4[i];
            uint32_t o = v.x | v.y | v.z | v.w;
            ge2 |= o & 0xFEFEFEFEu;     // any byte >= 2 anywhere -> float32
            odd |= o & 0xFFFFFF00u;     // any nonzero byte at idx%4 != 0 -> uint8
        }
        if (ge2) atomicOr(&f[0], 1);
        if (odd) atomicOr(&f[1], 1);
    }
    __syncthreads();

    // ---- canonical mask for this block's 64 entries ----
    if (t < 64) {
        const int kind = f[0] ? 2 : (f[1] ? 0 : 1);   // 0=u8, 1=i32, 2=f32
        const int i = blockIdx.x * 64 + t;
        bool m;
        if (kind == 0)      m = ((const unsigned char*)pad)[i] != 0;
        else if (kind == 1) m = ((const int*)pad)[i] != 0;
        else                m = ((const float*)pad)[i] != 0.f;
        g_padneg[i] = m ? __int_as_float(0xff800000) : 0.f;
    }

    u64_t e2[32];
    {
        const ulonglong2* er = reinterpret_cast<const ulonglong2*>(E + g * D_);
        #pragma unroll
        for (int i = 0; i < 16; i++) { ulonglong2 v = er[i]; e2[2*i] = v.x; e2[2*i+1] = v.y; }
    }

    const float* bsx[3] = {bq, bk, bv};
    __half* oh3[3] = {g_Qh, g_Kh, g_Vh};
    float outv[32];

    #pragma unroll
    for (int m = 0; m < 3; m++) {
        #pragma unroll 4
        for (int c = 0; c < 32; c++) {
            const ulonglong2* wr = reinterpret_cast<const ulonglong2*>(Wsm[m] + (cbase + c) * D_);
            u64_t a0 = 0ull, a1 = 0ull;
            #pragma unroll
            for (int d8 = 0; d8 < 16; d8++) {
                ulonglong2 w = wr[d8];
                a0 = fma2(e2[2*d8],   w.x, a0);
                a1 = fma2(e2[2*d8+1], w.y, a1);
            }
            float2 p0 = unpack2(a0), p1 = unpack2(a1);
            outv[c] = bsx[m][cbase + c] + ((p0.x + p0.y) + (p1.x + p1.y));
        }
        if (m == 0) {
            #pragma unroll
            for (int c = 0; c < 32; c++) outv[c] *= QSCALE;
        } else {
            const float* mod = (m == 1 ? PK : PV) + g * D_ + cbase;
            #pragma unroll
            for (int c = 0; c < 32; c++) outv[c] *= mod[c];
        }
        unsigned short hb[32];
        #pragma unroll
        for (int c = 0; c < 32; c++)
            hb[c] = __half_as_ushort(__float2half_rn(outv[c]));
        uint4* oh = reinterpret_cast<uint4*>(oh3[m] + g * D_ + cbase);
        const uint4* sh = reinterpret_cast<const uint4*>(hb);
        #pragma unroll
        for (int i = 0; i < 4; i++) oh[i] = sh[i];
    }

    // ---- meanV partial: outv holds this thread's half-row of fp32 V_p ----
    __syncthreads();                       // everyone done reading Wsm
    float* red = Wsm[0];                   // 64 x 64 f32 = 16 KB
    #pragma unroll
    for (int i = 0; i < 8; i++)
        reinterpret_cast<float4*>(red + rloc * 64 + cbase)[i] =
            make_float4(outv[4*i], outv[4*i+1], outv[4*i+2], outv[4*i+3]);
    __syncthreads();
    if (t < 64) {
        float a = 0.f;
        #pragma unroll 8
        for (int r = 0; r < 64; r++) a += red[r * 64 + t];
        g_part[blockIdx.x][t] = a;
    }
}

// ---------------------------------------------------------------------------
// Kernel 2: single-fp16 mma.sync flash attention, cp.async double-buffered.
// CTA = 256 threads = 4 row-warps x 2 key-halves over a 64-row q-tile
// (the round-8 measured-best core). Pair scheduling (qt, 63-qt): exactly 33
// k-tiles per CTA. meanV fallback computed in the prologue from g_part.
// ---------------------------------------------------------------------------
constexpr int SM_QH   = 0;                      // 64 x 128B
constexpr int SM_KV   = 8192;                   // 2 stages x (K 16KB + V 16KB)
constexpr int STG_SZ  = 32768;
constexpr int OFF_K   = 0, OFF_V = 16384;
constexpr int SM_PADB = SM_KV + 2 * STG_SZ;     // 73728, 2 x 512B
constexpr int SM_LSM  = SM_PADB + 1024;         // 74752, 2 x 64 f32
constexpr int SM_MNV  = SM_LSM + 512;           // 75264, 64 f32
constexpr int SM_MRG  = SM_KV;                  // merge overlays stage 0 (drained)
constexpr int SM_TOTAL = SM_MNV + 256;          // 75520

__global__ __launch_bounds__(256, 1) void attn_mma_kernel(float* __restrict__ out)
{
    extern __shared__ char sm[];
    const uint32_t smb = smem_u32(sm);
    const int tid = threadIdx.x, wid = tid >> 5, lane = tid & 31;
    const int wr = wid & 3, wc = wid >> 2;        // row-warp, key-half
    const int b = blockIdx.y;
    const int g8 = lane >> 3, l8 = lane & 7, l4 = lane >> 2, lq = lane & 3;
    float* lsm  = reinterpret_cast<float*>(sm + SM_LSM);
    float* mnv  = reinterpret_cast<float*>(sm + SM_MNV);
    float* mrg  = reinterpret_cast<float*>(sm + SM_MRG);

    // ---- meanV for this batch (sum of 64 proj-block partials) ----
    if (tid < 64) {
        float a = 0.f;
        #pragma unroll 8
        for (int i = 0; i < 64; i++) a += g_part[b * 64 + i][tid];
        mnv[tid] = a * (1.0f / (float)S_);
    }

    #pragma unroll 1
    for (int phase = 0; phase < 2; phase++) {
        const int qt = phase ? (63 - blockIdx.x) : blockIdx.x;
        const int qbase = qt * MT;
        const int nkt = (qt >> 1) + 1;

        __syncthreads();   // prev phase merge reads done (and mnv visible); smem reusable

        // ---- prologue: async-copy Q + k-tile 0 into stage 0 ----
        {
            const uint4* qh4 = reinterpret_cast<const uint4*>(g_Qh + ((size_t)b * S_ + qbase) * D_);
            #pragma unroll
            for (int it = 0; it < 2; it++) {
                int i = tid + it * 256;            // 512 chunks
                int row = i >> 3, c = i & 7;
                uint32_t sw = row * 128 + (((uint32_t)(c ^ (row & 7))) << 4);
                cpa16(smb + SM_QH + sw, qh4 + i);
            }
            const __half* srcs[2] = {g_Kh + (size_t)b * S_ * D_, g_Vh + (size_t)b * S_ * D_};
            #pragma unroll
            for (int t2 = 0; t2 < 2; t2++) {
                #pragma unroll
                for (int it = 0; it < 4; it++) {
                    int i = tid + it * 256;        // 1024 chunks per tile
                    int row = i >> 3, c = i & 7;
                    uint32_t dst = smb + SM_KV + t2 * 16384 + row * 128 + (((uint32_t)(c ^ (row & 7))) << 4);
                    cpa16(dst, reinterpret_cast<const uint4*>(srcs[t2]) + i);
                }
            }
            if (tid < 32)
                cpa16(smb + SM_PADB + tid * 16, (const char*)(g_padneg + b * S_) + tid * 16);
            CP_COMMIT();
        }
        CP_WAIT0();
        __syncthreads();

        // ---- Q A-fragments, 4 d-chunks of 16 ----
        uint32_t qh[4][4];
        {
            const int row = wr * 16 + (g8 & 1) * 8 + l8;
            #pragma unroll
            for (int dc = 0; dc < 4; dc++) {
                const int c = 2 * dc + (g8 >> 1);
                ldm_x4(qh[dc], smb + SM_QH + row * 128 + (((uint32_t)(c ^ (row & 7))) << 4));
            }
        }

        float OC[8][4];
        #pragma unroll
        for (int i = 0; i < 8; i++)
            { OC[i][0] = 0.f; OC[i][1] = 0.f; OC[i][2] = 0.f; OC[i][3] = 0.f; }
        float rs0 = 0.f, rs1 = 0.f;
        const int q0 = qbase + wr * 16 + l4, q1 = q0 + 8;
        const int kb0 = wc * 64;

        #pragma unroll 1
        for (int j = 0; j < nkt; j++) {
            const int st = j & 1;
            const uint32_t stb = smb + SM_KV + st * STG_SZ;
            const float* padsm = reinterpret_cast<const float*>(sm + SM_PADB + st * 512);
            const int kt = j * NT;

            // issue copy for tile j+1 into the other stage (overlaps compute)
            if (j + 1 < nkt) {
                const int ktn = (j + 1) * NT;
                const uint32_t nstb = smb + SM_KV + ((j + 1) & 1) * STG_SZ;
                const __half* srcs[2] = {g_Kh + ((size_t)b * S_ + ktn) * D_,
                                         g_Vh + ((size_t)b * S_ + ktn) * D_};
                #pragma unroll
                for (int t2 = 0; t2 < 2; t2++) {
                    #pragma unroll
                    for (int it = 0; it < 4; it++) {
                        int i = tid + it * 256;
                        int row = i >> 3, c = i & 7;
                        uint32_t dst = nstb + t2 * 16384 + row * 128 + (((uint32_t)(c ^ (row & 7))) << 4);
                        cpa16(dst, reinterpret_cast<const uint4*>(srcs[t2]) + i);
                    }
                }
                if (tid < 32)
                    cpa16(smb + SM_PADB + ((j + 1) & 1) * 512 + tid * 16,
                          (const char*)(g_padneg + b * S_ + ktn) + tid * 16);
                CP_COMMIT();
            }

            // ---- S = Q K^T (single fp16) ----
            float SC[8][4];
            #pragma unroll
            for (int i = 0; i < 8; i++)
                { SC[i][0] = 0.f; SC[i][1] = 0.f; SC[i][2] = 0.f; SC[i][3] = 0.f; }
            {
                const int krow0 = kb0 + (g8 >> 1) * 8 + l8;
                #pragma unroll
                for (int dc = 0; dc < 4; dc++) {
                    #pragma unroll
                    for (int kp = 0; kp < 4; kp++) {
                        const int row = krow0 + kp * 16;
                        const int c = 2 * dc + (g8 & 1);
                        uint32_t bh[4];
                        ldm_x4(bh, stb + OFF_K + row * 128 + (((uint32_t)(c ^ (row & 7))) << 4));
                        mma_f16(SC[2*kp],   qh[dc], bh);
                        mma_f16(SC[2*kp+1], qh[dc], bh + 2);
                    }
                }
            }

            // ---- mask + ex2 + C->A fragment conversion ----
            uint32_t Ph[4][4];
            if (j < nkt - 1) {
                #pragma unroll
                for (int n = 0; n < 8; n++) {
                    const int colb = kb0 + n * 8 + 2 * lq;
                    const float m0 = padsm[colb], m1 = padsm[colb + 1];
                    const float p00 = ex2(SC[n][0] + m0);
                    const float p01 = ex2(SC[n][1] + m1);
                    const float p10 = ex2(SC[n][2] + m0);
                    const float p11 = ex2(SC[n][3] + m1);
                    const uint32_t hA = cvt_f16x2(p01, p00);
                    const uint32_t hB = cvt_f16x2(p11, p10);
                    const float2 fA = __half22float2(*reinterpret_cast<const half2*>(&hA));
                    const float2 fB = __half22float2(*reinterpret_cast<const half2*>(&hB));
                    rs0 += fA.x + fA.y;
                    rs1 += fB.x + fB.y;
                    const int kc = n >> 1, sub = (n & 1) * 2;
                    Ph[kc][sub] = hA; Ph[kc][sub + 1] = hB;
                }
            } else {
                #pragma unroll
                for (int n = 0; n < 8; n++) {
                    const int colb = kb0 + n * 8 + 2 * lq;
                    const int key = kt + colb;
                    const float m0 = padsm[colb], m1 = padsm[colb + 1];
                    const float p00 = (key     <= q0) ? ex2(SC[n][0] + m0) : 0.f;
                    const float p01 = (key + 1 <= q0) ? ex2(SC[n][1] + m1) : 0.f;
                    const float p10 = (key     <= q1) ? ex2(SC[n][2] + m0) : 0.f;
                    const float p11 = (key + 1 <= q1) ? ex2(SC[n][3] + m1) : 0.f;
                    const uint32_t hA = cvt_f16x2(p01, p00);
                    const uint32_t hB = cvt_f16x2(p11, p10);
                    const float2 fA = __half22float2(*reinterpret_cast<const half2*>(&hA));
                    const float2 fB = __half22float2(*reinterpret_cast<const half2*>(&hB));
                    rs0 += fA.x + fA.y;
                    rs1 += fB.x + fB.y;
                    const int kc = n >> 1, sub = (n & 1) * 2;
                    Ph[kc][sub] = hA; Ph[kc][sub + 1] = hB;
                }
            }

            // ---- O += P V (V via ldmatrix.trans) ----
            {
                const int vrow0 = kb0 + (g8 & 1) * 8 + l8;
                #pragma unroll
                for (int kc = 0; kc < 4; kc++) {
                    #pragma unroll
                    for (int ndp = 0; ndp < 4; ndp++) {
                        const int row = vrow0 + kc * 16;
                        const int c = 2 * ndp + (g8 >> 1);
                        uint32_t bh[4];
                        ldm_x4_t(bh, stb + OFF_V + row * 128 + (((uint32_t)(c ^ (row & 7))) << 4));
                        mma_f16(OC[2*ndp],   Ph[kc], bh);
                        mma_f16(OC[2*ndp+1], Ph[kc], bh + 2);
                    }
                }
            }

            if (j + 1 < nkt) CP_WAIT0();
            __syncthreads();
        }

        // ---- merge the two key-halves (ADD; no rescaling needed) ----
        rs0 += __shfl_xor_sync(0xFFFFFFFFu, rs0, 1);
        rs0 += __shfl_xor_sync(0xFFFFFFFFu, rs0, 2);
        rs1 += __shfl_xor_sync(0xFFFFFFFFu, rs1, 1);
        rs1 += __shfl_xor_sync(0xFFFFFFFFu, rs1, 2);
        if (lq == 0) {
            lsm[wc * 64 + wr * 16 + l4]     = rs0;
            lsm[wc * 64 + wr * 16 + 8 + l4] = rs1;
        }
        if (wc == 1) {
            const int r0 = wr * 16 + l4;
            #pragma unroll
            for (int nd = 0; nd < 8; nd++) {
                const int d0 = nd * 8 + 2 * lq;
                *reinterpret_cast<float2*>(&mrg[r0 * 64 + d0])       = make_float2(OC[nd][0], OC[nd][1]);
                *reinterpret_cast<float2*>(&mrg[(r0 + 8) * 64 + d0]) = make_float2(OC[nd][2], OC[nd][3]);
            }
        }
        __syncthreads();
        if (wc == 0) {
            const int r0 = wr * 16 + l4;
            const float lt0 = lsm[r0] + lsm[64 + r0];
            const float lt1 = lsm[r0 + 8] + lsm[64 + r0 + 8];
            const bool am0 = (lt0 == 0.f), am1 = (lt1 == 0.f);
            const float inv0 = am0 ? 0.f : 1.f / lt0;
            const float inv1 = am1 ? 0.f : 1.f / lt1;
            const int qr0 = qbase + r0, qr1 = qr0 + 8;
            #pragma unroll
            for (int nd = 0; nd < 8; nd++) {
                const int d0 = nd * 8 + 2 * lq;
                const float2 m0v = *reinterpret_cast<const float2*>(&mrg[r0 * 64 + d0]);
                const float2 m1v = *reinterpret_cast<const float2*>(&mrg[(r0 + 8) * 64 + d0]);
                float2 o0, o1;
                if (am0) o0 = make_float2(mnv[d0], mnv[d0 + 1]);
                else     o0 = make_float2((OC[nd][0] + m0v.x) * inv0, (OC[nd][1] + m0v.y) * inv0);
                if (am1) o1 = make_float2(mnv[d0], mnv[d0 + 1]);
                else     o1 = make_float2((OC[nd][2] + m1v.x) * inv1, (OC[nd][3] + m1v.y) * inv1);
                *reinterpret_cast<float2*>(&out[((size_t)b * S_ + qr0) * D_ + d0]) = o0;
                *reinterpret_cast<float2*>(&out[((size_t)b * S_ + qr1) * D_ + d0]) = o1;
            }
        }
    }
}

// ---------------------------------------------------------------------------
extern "C" void kernel_launch(void* const* d_in, const int* in_sizes, int n_in,
                              void* d_out, int out_size)
{
    const float* E  = (const float*)d_in[0];
    const float* PK = (const float*)d_in[1];
    const float* PV = (const float*)d_in[2];
    const float* Wq = (const float*)d_in[3];
    const float* bq = (const float*)d_in[4];
    const float* Wk = (const float*)d_in[5];
    const float* bk = (const float*)d_in[6];
    const float* Wv = (const float*)d_in[7];
    const float* bv = (const float*)d_in[8];
    const void*  pad = d_in[9];
    float* out = (float*)d_out;

    cudaFuncSetAttribute(attn_mma_kernel, cudaFuncAttributeMaxDynamicSharedMemorySize, SM_TOTAL);

    proj_kernel<<<256, 128>>>(E, PK, PV, Wq, bq, Wk, bk, Wv, bv, pad);
    attn_mma_kernel<<<dim3(32, B_), 256, SM_TOTAL>>>(out);
}

// round 11
// speedup vs baseline: 1.1184x; 1.0502x over previous
#include <cuda_runtime.h>
#include <cuda_fp16.h>
#include <math.h>
#include <stdint.h>

// Problem constants
constexpr int B_ = 4, S_ = 4096, D_ = 64;
constexpr int MT = 64;            // q rows per tile (one phase)
constexpr int NT = 128;           // keys per k-tile
constexpr float QSCALE = 0.18033688011112042f;  // 0.125 * log2(e), folded into Q

// ---- global scratch (allocation-free rule) ----
__device__ __align__(16) __half g_Qh[B_*S_*D_];
__device__ __align__(16) __half g_Kh[B_*S_*D_];   // zeroed on padded keys
__device__ __align__(16) __half g_Vh[B_*S_*D_];   // zeroed on padded keys
__device__ __align__(16) __half g_pad1h[B_*S_];   // 1.0 keep / 0.0 masked
__device__ float g_part[256][D_];                 // V_p column sums per proj block

// ---- f32x2 helpers (proj kernel) ----
using u64_t = unsigned long long;
__device__ __forceinline__ u64_t fma2(u64_t a, u64_t b, u64_t c) {
    u64_t d; asm("fma.rn.f32x2 %0, %1, %2, %3;" : "=l"(d) : "l"(a), "l"(b), "l"(c)); return d;
}
__device__ __forceinline__ float2 unpack2(u64_t v) {
    float2 r; asm("mov.b64 {%0, %1}, %2;" : "=f"(r.x), "=f"(r.y) : "l"(v)); return r;
}

__device__ __forceinline__ uint32_t smem_u32(const void* p) {
    uint32_t a;
    asm("{ .reg .u64 t; cvta.to.shared.u64 t, %1; cvt.u32.u64 %0, t; }" : "=r"(a) : "l"(p));
    return a;
}

// ---- mma.sync / ldmatrix / misc PTX ----
__device__ __forceinline__ void ldm_x4(uint32_t* r, uint32_t a) {
    asm volatile("ldmatrix.sync.aligned.m8n8.x4.shared.b16 {%0,%1,%2,%3}, [%4];"
                 : "=r"(r[0]), "=r"(r[1]), "=r"(r[2]), "=r"(r[3]) : "r"(a));
}
__device__ __forceinline__ void ldm_x4_t(uint32_t* r, uint32_t a) {
    asm volatile("ldmatrix.sync.aligned.m8n8.x4.trans.shared.b16 {%0,%1,%2,%3}, [%4];"
                 : "=r"(r[0]), "=r"(r[1]), "=r"(r[2]), "=r"(r[3]) : "r"(a));
}
__device__ __forceinline__ void mma_f16(float* c, const uint32_t* a, const uint32_t* b) {
    asm volatile("mma.sync.aligned.m16n8k16.row.col.f32.f16.f16.f32 "
                 "{%0,%1,%2,%3}, {%4,%5,%6,%7}, {%8,%9}, {%0,%1,%2,%3};"
                 : "+f"(c[0]), "+f"(c[1]), "+f"(c[2]), "+f"(c[3])
                 : "r"(a[0]), "r"(a[1]), "r"(a[2]), "r"(a[3]), "r"(b[0]), "r"(b[1]));
}
__device__ __forceinline__ float ex2(float x) {
    float y; asm("ex2.approx.f32 %0, %1;" : "=f"(y) : "f"(x)); return y;
}
// pack two fp32 -> fp16x2; second arg lands in the LOW half
__device__ __forceinline__ uint32_t cvt_f16x2(float hi, float lo) {
    uint32_t r; asm("cvt.rn.f16x2.f32 %0, %1, %2;" : "=r"(r) : "f"(hi), "f"(lo)); return r;
}
__device__ __forceinline__ uint32_t lds32(uint32_t a) {
    uint32_t v; asm volatile("ld.shared.b32 %0, [%1];" : "=r"(v) : "r"(a)); return v;
}
__device__ __forceinline__ void cpa16(uint32_t dst, const void* src) {
    asm volatile("cp.async.cg.shared.global [%0], [%1], 16;" :: "r"(dst), "l"(src));
}
#define CP_COMMIT() asm volatile("cp.async.commit_group;" ::: "memory")
#define CP_WAIT0()  asm volatile("cp.async.wait_group 0;" ::: "memory")

// ---------------------------------------------------------------------------
// Kernel 1: fused pad canonicalization + QKV projection + popularity
// modulation -> single fp16 (padded K/V rows zeroed at the fp16 store),
// plus per-block UN-zeroed V_p column sums (for the meanV fallback).
// 256 blocks x 128 threads; 2 threads per row (32 output features each).
// ---------------------------------------------------------------------------
__global__ __launch_bounds__(128) void proj_kernel(
    const float* __restrict__ E,  const float* __restrict__ PK, const float* __restrict__ PV,
    const float* __restrict__ Wq, const float* __restrict__ bq,
    const float* __restrict__ Wk, const float* __restrict__ bk,
    const float* __restrict__ Wv, const float* __restrict__ bv,
    const void* __restrict__ pad)
{
    __shared__ float Wsm[3][D_ * D_];     // 48 KB; Wsm[0] reused as reduction scratch
    __shared__ float keepf[64];
    __shared__ int f[2];
    const int t = threadIdx.x;
    const int rloc = t & 63, chalf = t >> 6;
    const int cbase = chalf * 32;
    const size_t g = (size_t)blockIdx.x * 64 + rloc;

    if (t < 2) f[t] = 0;

    // ---- stage W matrices ----
    {
        const float* Ws[3] = {Wq, Wk, Wv};
        #pragma unroll
        for (int m = 0; m < 3; m++) {
            float4* dst = reinterpret_cast<float4*>(Wsm[m]);
            const float4* src = reinterpret_cast<const float4*>(Ws[m]);
            #pragma unroll
            for (int i = 0; i < 8; i++) dst[t + i * 128] = src[t + i * 128];
        }
    }

    // ---- pad dtype detection (independent per block; 16KB scan = min buffer) ----
    {
        const uint4* p4 = reinterpret_cast<const uint4*>(pad);   // 1024 x 16B
        uint32_t ge2 = 0, odd = 0;
        #pragma unroll
        for (int i = t; i < 1024; i += 128) {
            uint4 v = p4[i];
            uint32_t o = v.x | v.y | v.z | v.w;
            ge2 |= o & 0xFEFEFEFEu;     // any byte >= 2 anywhere -> float32
            odd |= o & 0xFFFFFF00u;     // any nonzero byte at idx%4 != 0 -> uint8
        }
        if (ge2) atomicOr(&f[0], 1);
        if (odd) atomicOr(&f[1], 1);
    }
    __syncthreads();

    // ---- canonical half mask + keep flags for this block's 64 rows ----
    if (t < 64) {
        const int kind = f[0] ? 2 : (f[1] ? 0 : 1);   // 0=u8, 1=i32, 2=f32
        const int i = blockIdx.x * 64 + t;
        bool m;
        if (kind == 0)      m = ((const unsigned char*)pad)[i] != 0;
        else if (kind == 1) m = ((const int*)pad)[i] != 0;
        else                m = ((const float*)pad)[i] != 0.f;
        const float k = m ? 0.f : 1.f;
        keepf[t] = k;
        g_pad1h[i] = __float2half(k);
    }
    __syncthreads();

    u64_t e2[32];
    {
        const ulonglong2* er = reinterpret_cast<const ulonglong2*>(E + g * D_);
        #pragma unroll
        for (int i = 0; i < 16; i++) { ulonglong2 v = er[i]; e2[2*i] = v.x; e2[2*i+1] = v.y; }
    }

    const float keep = keepf[rloc];
    const float* bsx[3] = {bq, bk, bv};
    __half* oh3[3] = {g_Qh, g_Kh, g_Vh};
    float outv[32];

    #pragma unroll
    for (int m = 0; m < 3; m++) {
        #pragma unroll 4
        for (int c = 0; c < 32; c++) {
            const ulonglong2* wr = reinterpret_cast<const ulonglong2*>(Wsm[m] + (cbase + c) * D_);
            u64_t a0 = 0ull, a1 = 0ull;
            #pragma unroll
            for (int d8 = 0; d8 < 16; d8++) {
                ulonglong2 w = wr[d8];
                a0 = fma2(e2[2*d8],   w.x, a0);
                a1 = fma2(e2[2*d8+1], w.y, a1);
            }
            float2 p0 = unpack2(a0), p1 = unpack2(a1);
            outv[c] = bsx[m][cbase + c] + ((p0.x + p0.y) + (p1.x + p1.y));
        }
        if (m == 0) {
            #pragma unroll
            for (int c = 0; c < 32; c++) outv[c] *= QSCALE;
        } else {
            const float* mod = (m == 1 ? PK : PV) + g * D_ + cbase;
            #pragma unroll
            for (int c = 0; c < 32; c++) outv[c] *= mod[c];
        }
        // fp16 store; K/V rows of padded keys are zeroed HERE (outv stays
        // unzeroed so the meanV partial below uses the true V_p)
        const float zf = (m == 0) ? 1.f : keep;
        unsigned short hb[32];
        #pragma unroll
        for (int c = 0; c < 32; c++)
            hb[c] = __half_as_ushort(__float2half_rn(outv[c] * zf));
        uint4* oh = reinterpret_cast<uint4*>(oh3[m] + g * D_ + cbase);
        const uint4* sh = reinterpret_cast<const uint4*>(hb);
        #pragma unroll
        for (int i = 0; i < 4; i++) oh[i] = sh[i];
    }

    // ---- meanV partial: outv holds this thread's half-row of fp32 V_p ----
    __syncthreads();                       // everyone done reading Wsm
    float* red = Wsm[0];                   // 64 x 64 f32 = 16 KB
    #pragma unroll
    for (int i = 0; i < 8; i++)
        reinterpret_cast<float4*>(red + rloc * 64 + cbase)[i] =
            make_float4(outv[4*i], outv[4*i+1], outv[4*i+2], outv[4*i+3]);
    __syncthreads();
    if (t < 64) {
        float a = 0.f;
        #pragma unroll 8
        for (int r = 0; r < 64; r++) a += red[r * 64 + t];
        g_part[blockIdx.x][t] = a;
    }
}

// ---------------------------------------------------------------------------
// Kernel 2: single-fp16 mma.sync flash attention, cp.async double-buffered.
// CTA = 256 threads = 4 row-warps x 2 key-halves over a 64-row q-tile.
// Pair scheduling (qt, 63-qt): exactly 33 k-tiles per CTA.
// Padding handled entirely in the GEMMs: K/V rows zeroed (so padded s=0,
// p=1) and l accumulated by an extra MMA against the 1/0 half mask, so the
// per-element epilogue is pure ex2+cvt. Fully-masked rows give l==0 exactly.
// ---------------------------------------------------------------------------
constexpr int SM_QH   = 0;                      // 64 x 128B
constexpr int SM_KV   = 8192;                   // 2 stages x (K 16KB + V 16KB)
constexpr int STG_SZ  = 32768;
constexpr int OFF_K   = 0, OFF_V = 16384;
constexpr int SM_PADB = SM_KV + 2 * STG_SZ;     // 73728, 2 x 256B (half mask)
constexpr int SM_LSM  = SM_PADB + 512;          // 74240, 2 x 64 f32
constexpr int SM_MNV  = SM_LSM + 512;           // 74752, 64 f32
constexpr int SM_MRG  = SM_KV;                  // merge overlays stage 0 (drained)
constexpr int SM_TOTAL = SM_MNV + 256;          // 75008

__global__ __launch_bounds__(256, 1) void attn_mma_kernel(float* __restrict__ out)
{
    extern __shared__ char sm[];
    const uint32_t smb = smem_u32(sm);
    const int tid = threadIdx.x, wid = tid >> 5, lane = tid & 31;
    const int wr = wid & 3, wc = wid >> 2;        // row-warp, key-half
    const int b = blockIdx.y;
    const int g8 = lane >> 3, l8 = lane & 7, l4 = lane >> 2, lq = lane & 3;
    float* lsm  = reinterpret_cast<float*>(sm + SM_LSM);
    float* mnv  = reinterpret_cast<float*>(sm + SM_MNV);
    float* mrg  = reinterpret_cast<float*>(sm + SM_MRG);

    // ---- meanV for this batch (sum of 64 proj-block partials) ----
    if (tid < 64) {
        float a = 0.f;
        #pragma unroll 8
        for (int i = 0; i < 64; i++) a += g_part[b * 64 + i][tid];
        mnv[tid] = a * (1.0f / (float)S_);
    }

    #pragma unroll 1
    for (int phase = 0; phase < 2; phase++) {
        const int qt = phase ? (63 - blockIdx.x) : blockIdx.x;
        const int qbase = qt * MT;
        const int nkt = (qt >> 1) + 1;

        __syncthreads();   // prev phase merge reads done (and mnv visible); smem reusable

        // ---- prologue: async-copy Q + k-tile 0 into stage 0 ----
        {
            const uint4* qh4 = reinterpret_cast<const uint4*>(g_Qh + ((size_t)b * S_ + qbase) * D_);
            #pragma unroll
            for (int it = 0; it < 2; it++) {
                int i = tid + it * 256;            // 512 chunks
                int row = i >> 3, c = i & 7;
                uint32_t sw = row * 128 + (((uint32_t)(c ^ (row & 7))) << 4);
                cpa16(smb + SM_QH + sw, qh4 + i);
            }
            const __half* srcs[2] = {g_Kh + (size_t)b * S_ * D_, g_Vh + (size_t)b * S_ * D_};
            #pragma unroll
            for (int t2 = 0; t2 < 2; t2++) {
                #pragma unroll
                for (int it = 0; it < 4; it++) {
                    int i = tid + it * 256;        // 1024 chunks per tile
                    int row = i >> 3, c = i & 7;
                    uint32_t dst = smb + SM_KV + t2 * 16384 + row * 128 + (((uint32_t)(c ^ (row & 7))) << 4);
                    cpa16(dst, reinterpret_cast<const uint4*>(srcs[t2]) + i);
                }
            }
            if (tid < 16)
                cpa16(smb + SM_PADB + tid * 16, (const char*)(g_pad1h + b * S_) + tid * 16);
            CP_COMMIT();
        }
        CP_WAIT0();
        __syncthreads();

        // ---- Q A-fragments, 4 d-chunks of 16 ----
        uint32_t qh[4][4];
        {
            const int row = wr * 16 + (g8 & 1) * 8 + l8;
            #pragma unroll
            for (int dc = 0; dc < 4; dc++) {
                const int c = 2 * dc + (g8 >> 1);
                ldm_x4(qh[dc], smb + SM_QH + row * 128 + (((uint32_t)(c ^ (row & 7))) << 4));
            }
        }

        float OC[8][4];
        #pragma unroll
        for (int i = 0; i < 8; i++)
            { OC[i][0] = 0.f; OC[i][1] = 0.f; OC[i][2] = 0.f; OC[i][3] = 0.f; }
        float LM[4] = {0.f, 0.f, 0.f, 0.f};   // l accumulator (MMA C-fragment)
        const int q0 = qbase + wr * 16 + l4, q1 = q0 + 8;
        const int kb0 = wc * 64;

        #pragma unroll 1
        for (int j = 0; j < nkt; j++) {
            const int st = j & 1;
            const uint32_t stb = smb + SM_KV + st * STG_SZ;
            const uint32_t padb = smb + SM_PADB + st * 256;
            const int kt = j * NT;

            // issue copy for tile j+1 into the other stage (overlaps compute)
            if (j + 1 < nkt) {
                const int ktn = (j + 1) * NT;
                const uint32_t nstb = smb + SM_KV + ((j + 1) & 1) * STG_SZ;
                const __half* srcs[2] = {g_Kh + ((size_t)b * S_ + ktn) * D_,
                                         g_Vh + ((size_t)b * S_ + ktn) * D_};
                #pragma unroll
                for (int t2 = 0; t2 < 2; t2++) {
                    #pragma unroll
                    for (int it = 0; it < 4; it++) {
                        int i = tid + it * 256;
                        int row = i >> 3, c = i & 7;
                        uint32_t dst = nstb + t2 * 16384 + row * 128 + (((uint32_t)(c ^ (row & 7))) << 4);
                        cpa16(dst, reinterpret_cast<const uint4*>(srcs[t2]) + i);
                    }
                }
                if (tid < 16)
                    cpa16(smb + SM_PADB + ((j + 1) & 1) * 256 + tid * 16,
                          (const char*)(g_pad1h + b * S_ + ktn) + tid * 16);
                CP_COMMIT();
            }

            // ---- S = Q K^T (single fp16) ----
            float SC[8][4];
            #pragma unroll
            for (int i = 0; i < 8; i++)
                { SC[i][0] = 0.f; SC[i][1] = 0.f; SC[i][2] = 0.f; SC[i][3] = 0.f; }
            {
                const int krow0 = kb0 + (g8 >> 1) * 8 + l8;
                #pragma unroll
                for (int dc = 0; dc < 4; dc++) {
                    #pragma unroll
                    for (int kp = 0; kp < 4; kp++) {
                        const int row = krow0 + kp * 16;
                        const int c = 2 * dc + (g8 & 1);
                        uint32_t bh[4];
                        ldm_x4(bh, stb + OFF_K + row * 128 + (((uint32_t)(c ^ (row & 7))) << 4));
                        mma_f16(SC[2*kp],   qh[dc], bh);
                        mma_f16(SC[2*kp+1], qh[dc], bh + 2);
                    }
                }
            }

            // ---- ex2 + C->A fragment conversion (pad folded into GEMMs) ----
            uint32_t Ph[4][4];
            if (j < nkt - 1) {
                #pragma unroll
                for (int n = 0; n < 8; n++) {
                    const float p00 = ex2(SC[n][0]);
                    const float p01 = ex2(SC[n][1]);
                    const float p10 = ex2(SC[n][2]);
                    const float p11 = ex2(SC[n][3]);
                    const int kc = n >> 1, sub = (n & 1) * 2;
                    Ph[kc][sub]     = cvt_f16x2(p01, p00);
                    Ph[kc][sub + 1] = cvt_f16x2(p11, p10);
                }
            } else {
                #pragma unroll
                for (int n = 0; n < 8; n++) {
                    const int key = kt + kb0 + n * 8 + 2 * lq;
                    const float p00 = (key     <= q0) ? ex2(SC[n][0]) : 0.f;
                    const float p01 = (key + 1 <= q0) ? ex2(SC[n][1]) : 0.f;
                    const float p10 = (key     <= q1) ? ex2(SC[n][2]) : 0.f;
                    const float p11 = (key + 1 <= q1) ? ex2(SC[n][3]) : 0.f;
                    const int kc = n >> 1, sub = (n & 1) * 2;
                    Ph[kc][sub]     = cvt_f16x2(p01, p00);
                    Ph[kc][sub + 1] = cvt_f16x2(p11, p10);
                }
            }

            // ---- l += P . mask (one n=8 MMA per 16-key chunk) ----
            {
                #pragma unroll
                for (int kc = 0; kc < 4; kc++) {
                    const uint32_t a = padb + (uint32_t)(kb0 + kc * 16 + 2 * lq) * 2;
                    uint32_t bm[2];
                    bm[0] = lds32(a);
                    bm[1] = lds32(a + 16);
                    mma_f16(LM, Ph[kc], bm);
                }
            }

            // ---- O += P V (V via ldmatrix.trans) ----
            {
                const int vrow0 = kb0 + (g8 & 1) * 8 + l8;
                #pragma unroll
                for (int kc = 0; kc < 4; kc++) {
                    #pragma unroll
                    for (int ndp = 0; ndp < 4; ndp++) {
                        const int row = vrow0 + kc * 16;
                        const int c = 2 * ndp + (g8 >> 1);
                        uint32_t bh[4];
                        ldm_x4_t(bh, stb + OFF_V + row * 128 + (((uint32_t)(c ^ (row & 7))) << 4));
                        mma_f16(OC[2*ndp],   Ph[kc], bh);
                        mma_f16(OC[2*ndp+1], Ph[kc], bh + 2);
                    }
                }
            }

            if (j + 1 < nkt) CP_WAIT0();
            __syncthreads();
        }

        // ---- merge the two key-halves (ADD; no rescaling needed) ----
        // LM cols are identical (mask B same across n): LM[0]=l(q0), LM[2]=l(q1)
        if (lq == 0) {
            lsm[wc * 64 + wr * 16 + l4]     = LM[0];
            lsm[wc * 64 + wr * 16 + 8 + l4] = LM[2];
        }
        if (wc == 1) {
            const int r0 = wr * 16 + l4;
            #pragma unroll
            for (int nd = 0; nd < 8; nd++) {
                const int d0 = nd * 8 + 2 * lq;
                *reinterpret_cast<float2*>(&mrg[r0 * 64 + d0])       = make_float2(OC[nd][0], OC[nd][1]);
                *reinterpret_cast<float2*>(&mrg[(r0 + 8) * 64 + d0]) = make_float2(OC[nd][2], OC[nd][3]);
            }
        }
        __syncthreads();
        if (wc == 0) {
            const int r0 = wr * 16 + l4;
            const float lt0 = lsm[r0] + lsm[64 + r0];
            const float lt1 = lsm[r0 + 8] + lsm[64 + r0 + 8];
            const bool am0 = (lt0 == 0.f), am1 = (lt1 == 0.f);
            const float inv0 = am0 ? 0.f : 1.f / lt0;
            const float inv1 = am1 ? 0.f : 1.f / lt1;
            const int qr0 = qbase + r0, qr1 = qr0 + 8;
            #pragma unroll
            for (int nd = 0; nd < 8; nd++) {
                const int d0 = nd * 8 + 2 * lq;
                const float2 m0v = *reinterpret_cast<const float2*>(&mrg[r0 * 64 + d0]);
                const float2 m1v = *reinterpret_cast<const float2*>(&mrg[(r0 + 8) * 64 + d0]);
                float2 o0, o1;
                if (am0) o0 = make_float2(mnv[d0], mnv[d0 + 1]);
                else     o0 = make_float2((OC[nd][0] + m0v.x) * inv0, (OC[nd][1] + m0v.y) * inv0);
                if (am1) o1 = make_float2(mnv[d0], mnv[d0 + 1]);
                else     o1 = make_float2((OC[nd][2] + m1v.x) * inv1, (OC[nd][3] + m1v.y) * inv1);
                *reinterpret_cast<float2*>(&out[((size_t)b * S_ + qr0) * D_ + d0]) = o0;
                *reinterpret_cast<float2*>(&out[((size_t)b * S_ + qr1) * D_ + d0]) = o1;
            }
        }
    }
}

// ---------------------------------------------------------------------------
extern "C" void kernel_launch(void* const* d_in, const int* in_sizes, int n_in,
                              void* d_out, int out_size)
{
    const float* E  = (const float*)d_in[0];
    const float* PK = (const float*)d_in[1];
    const float* PV = (const float*)d_in[2];
    const float* Wq = (const float*)d_in[3];
    const float* bq = (const float*)d_in[4];
    const float* Wk = (const float*)d_in[5];
    const float* bk = (const float*)d_in[6];
    const float* Wv = (const float*)d_in[7];
    const float* bv = (const float*)d_in[8];
    const void*  pad = d_in[9];
    float* out = (float*)d_out;

    cudaFuncSetAttribute(attn_mma_kernel, cudaFuncAttributeMaxDynamicSharedMemorySize, SM_TOTAL);

    proj_kernel<<<256, 128>>>(E, PK, PV, Wq, bq, Wk, bk, Wv, bv, pad);
    attn_mma_kernel<<<dim3(32, B_), 256, SM_TOTAL>>>(out);
}